// round 4
// baseline (speedup 1.0000x reference)
#include <cuda_runtime.h>
#include <cuda_bf16.h>
#include <math.h>

#define IMG_H 512
#define IMG_W 640
#define HW (IMG_H * IMG_W)            // 327680
#define FXc 500.0f
#define FYc 500.0f
#define CXc 320.0f
#define CYc 256.0f

#define SCAN_BLK 1024
#define NSCAN_BLOCKS (HW / SCAN_BLK)  // 320

#define NPAD 524288                   // 2^19 >= n_valid (~345k), power of two
#define NCHUNK 256                    // NPAD / 2048
#define KMAX 24                       // register-sort cap (Poisson lambda~1.05)

// ---------------- device scratch ----------------
__device__ unsigned int g_cntbuf[HW + 1];   // [HW] = nvalid append counter
__device__ unsigned int g_off[HW];
__device__ unsigned int g_woff[HW];
__device__ unsigned int g_bsum[NSCAN_BLOCKS];

__device__ float4 g_rec[NPAD];   // unordered: {pid_bits, z, w, idx_bits}
__device__ float4 g_srec[NPAD];  // binned+sorted: {z, w, idx_bits, unused}

__device__ float g_x[NPAD];      // lg = log1p(-w) at sorted positions (zero padded)
__device__ float g_S[NPAD];      // inclusive scan, assoc-scan rounding replicated
__device__ float g_L11[NCHUNK];
__device__ float g_S11[NCHUNK];

// ---------------- pass 1: project once, count + append compact records ----
// Projection arithmetic must be bit-identical to R1 (measured best):
// separate __fmul_rn/__fadd_rn, NO fma contraction.
__global__ void project_count_kernel(const float* __restrict__ means,
                                     const float* __restrict__ opac,
                                     const float* __restrict__ pose, int n)
{
    int i = blockIdx.x * blockDim.x + threadIdx.x;
    bool valid = false;
    float z = 0.0f;
    int pid = 0;
    if (i < n) {
        float m0 = means[3 * i + 0];
        float m1 = means[3 * i + 1];
        float m2 = means[3 * i + 2];
        // pose is identity: exact regardless of order
        float pc0 = m0 * pose[0] + m1 * pose[1] + m2 * pose[2]  + pose[3];
        float pc1 = m0 * pose[4] + m1 * pose[5] + m2 * pose[6]  + pose[7];
        z         = m0 * pose[8] + m1 * pose[9] + m2 * pose[10] + pose[11];
        // IEEE rn div/mul/add, NO fma (matches reference; R1-verified)
        float x = __fadd_rn(__fmul_rn(__fdiv_rn(pc0, z), FXc), CXc);
        float y = __fadd_rn(__fmul_rn(__fdiv_rn(pc1, z), FYc), CYc);
        valid = (x >= 0.0f) && (x < (float)IMG_W) &&
                (y >= 0.0f) && (y < (float)IMG_H) && (z > 0.0f);
        if (valid) {
            int xi = (int)floorf(x);
            int yi = (int)floorf(y);
            pid = yi * IMG_W + xi;
        }
    }
    unsigned int mask = __ballot_sync(0xffffffffu, valid);
    if (mask == 0u) return;
    int lane = threadIdx.x & 31;
    int leader = __ffs(mask) - 1;
    unsigned int base = 0;
    if (lane == leader)
        base = atomicAdd(&g_cntbuf[HW], (unsigned int)__popc(mask));
    base = __shfl_sync(0xffffffffu, base, leader);
    if (valid) {
        unsigned int pos = base + __popc(mask & ((1u << lane) - 1u));
        atomicAdd(&g_cntbuf[pid], 1u);
        if (pos < NPAD)
            g_rec[pos] = make_float4(__int_as_float(pid), z, opac[i],
                                     __int_as_float(i));
    }
}

// ---------------- offset scan: block sums ----------------
__global__ void scan_reduce_kernel()
{
    __shared__ unsigned int sh[SCAN_BLK];
    int t = threadIdx.x;
    sh[t] = g_cntbuf[blockIdx.x * SCAN_BLK + t];
    __syncthreads();
    for (int d = SCAN_BLK / 2; d > 0; d >>= 1) {
        if (t < d) sh[t] += sh[t + d];
        __syncthreads();
    }
    if (t == 0) g_bsum[blockIdx.x] = sh[0];
}

// ---------------- offset scan: full (redundant top scan per block) --------
__global__ void scan_offsets_kernel()
{
    __shared__ unsigned int sh[SCAN_BLK];
    __shared__ unsigned int tb[512];
    int t = threadIdx.x;
    int gi = blockIdx.x * SCAN_BLK + t;
    unsigned int v = g_cntbuf[gi];
    sh[t] = v;
    if (t < 512) tb[t] = (t < NSCAN_BLOCKS) ? g_bsum[t] : 0u;
    __syncthreads();
#pragma unroll
    for (int d = 1; d < SCAN_BLK; d <<= 1) {
        unsigned int add = (t >= d) ? sh[t - d] : 0u;
        unsigned int addt = (t < 512 && t >= d) ? tb[t - d] : 0u;
        __syncthreads();
        sh[t] += add;
        if (t < 512 && d < 512) tb[t] += addt;
        __syncthreads();
    }
    unsigned int bpref = (blockIdx.x > 0) ? tb[blockIdx.x - 1] : 0u;
    unsigned int o = sh[t] - v + bpref;
    g_off[gi] = o;
    g_woff[gi] = o;
}

// ---------------- pass 2: place records into bins ----------------
__global__ void place_kernel()
{
    unsigned int r = blockIdx.x * blockDim.x + threadIdx.x;
    if (r >= g_cntbuf[HW] || r >= NPAD) return;
    float4 rec = g_rec[r];
    int pid = __float_as_int(rec.x);
    unsigned int pos = atomicAdd(&g_woff[pid], 1u);
    if (pos < NPAD)
        g_srec[pos] = make_float4(rec.y, rec.z, rec.w, 0.0f);
}

// ---------------- per-pixel sort (z desc, idx asc) + emit lg --------------
__device__ __forceinline__ bool rec_before(const float4& a, const float4& b)
{
    if (a.x != b.x) return a.x > b.x;                   // z desc
    return __float_as_uint(a.z) < __float_as_uint(b.z); // idx asc (stable tie)
}

__global__ void sortemit_kernel()
{
    int p = blockIdx.x * blockDim.x + threadIdx.x;
    if (p >= HW) return;
    unsigned int s = g_off[p];
    unsigned int k = g_cntbuf[p];
    if (k == 0) return;
    if (k <= KMAX) {
        float4 a[KMAX];
        for (unsigned int i = 0; i < k; i++) a[i] = g_srec[s + i];
        for (unsigned int i = 1; i < k; i++) {
            float4 key = a[i];
            int j = (int)i - 1;
            while (j >= 0 && rec_before(key, a[j])) { a[j + 1] = a[j]; j--; }
            a[j + 1] = key;
        }
        for (unsigned int i = 0; i < k; i++) {
            g_srec[s + i] = a[i];
            g_x[s + i] = log1pf(-a[i].y);
        }
    } else {
        for (unsigned int i = 0; i < k; i++) {
            unsigned int best = i;
            float4 bv = g_srec[s + i];
            for (unsigned int j = i + 1; j < k; j++) {
                float4 cv = g_srec[s + j];
                if (rec_before(cv, bv)) { best = j; bv = cv; }
            }
            if (best != i) {
                float4 tmp = g_srec[s + i];
                g_srec[s + i] = bv;
                g_srec[s + best] = tmp;
            }
            g_x[s + i] = log1pf(-bv.y);
        }
    }
}

// ---------------- scan A: per-chunk pairwise tree sum (levels 1..11) ------
__global__ void scan_down_kernel()
{
    __shared__ float sh[2048];
    int t = threadIdx.x;               // 1024
    int base = blockIdx.x * 2048;
    sh[t] = g_x[base + t];
    sh[t + 1024] = g_x[base + t + 1024];
    __syncthreads();
    for (int size = 1024; size >= 1; size >>= 1) {
        float v = 0.0f;
        if (t < size) v = sh[2 * t] + sh[2 * t + 1];
        __syncthreads();
        if (t < size) sh[t] = v;
        __syncthreads();
    }
    if (t == 0) g_L11[blockIdx.x] = sh[0];
}

// ---------------- scan B: levels 12..19 + S11 (single block) --------------
__global__ void scan_mid_kernel()
{
    __shared__ float Lv[511];
    __shared__ float Sv[511];
    int t = threadIdx.x;               // 256
    Lv[t] = g_L11[t];
    __syncthreads();
    int off = 0, size = 256;
    for (int d = 0; d < 8; d++) {
        int noff = off + size, nsz = size >> 1;
        if (t < nsz) Lv[noff + t] = Lv[off + 2 * t] + Lv[off + 2 * t + 1];
        __syncthreads();
        off = noff; size = nsz;
    }
    if (t == 0) Sv[510] = Lv[510];
    __syncthreads();
    for (int d = 0; d < 8; d++) {
        int sz = 2 << d;
        off -= sz;
        int poff = off + sz;
        if (t < sz) {
            float v;
            if (t == 0)      v = Lv[off];
            else if (t & 1)  v = Sv[poff + ((t - 1) >> 1)];
            else             v = Sv[poff + (t >> 1) - 1] + Lv[off + t];
            Sv[off + t] = v;
        }
        __syncthreads();
    }
    g_S11[t] = Sv[t];
}

// ---------------- scan C: up-sweep, writes S (level 0) --------------------
__global__ void scan_up_kernel()
{
    __shared__ float Lb[4094];
    __shared__ float Sa[2048];
    __shared__ float Sb[1024];
    int t = threadIdx.x;               // 1024
    int b = blockIdx.x;
    int base = b * 2048;
    Lb[t] = g_x[base + t];
    Lb[t + 1024] = g_x[base + t + 1024];
    __syncthreads();
    int off = 0, size = 2048;
    for (int d = 1; d <= 10; d++) {
        int noff = off + size, nsz = size >> 1;
        for (int j = t; j < nsz; j += 1024)
            Lb[noff + j] = Lb[off + 2 * j] + Lb[off + 2 * j + 1];
        __syncthreads();
        off = noff; size = nsz;
    }
    float bound = (b > 0) ? g_S11[b - 1] : 0.0f;
    if (t == 0) {
        Sa[0] = (b == 0) ? Lb[off] : bound + Lb[off];
        Sa[1] = g_S11[b];
    }
    __syncthreads();
    for (int d = 9; d >= 0; d--) {
        int sz = 2048 >> d;
        off -= sz;
        float* Sprev = (d & 1) ? Sa : Sb;
        float* Scur  = (d & 1) ? Sb : Sa;
        for (int j = t; j < sz; j += 1024) {
            float v;
            if (j == 0)      v = (b == 0) ? Lb[off] : bound + Lb[off];
            else if (j & 1)  v = Sprev[(j - 1) >> 1];
            else             v = Sprev[(j >> 1) - 1] + Lb[off + j];
            Scur[j] = v;
        }
        __syncthreads();
    }
    g_S[base + t] = Sa[t];
    g_S[base + t + 1024] = Sa[t + 1024];
}

// ---------------- render ----------------
__global__ void render_kernel(const float* __restrict__ feats,
                              float* __restrict__ out)
{
    int p = blockIdx.x * blockDim.x + threadIdx.x;
    if (p >= HW) return;
    unsigned int s = g_off[p];
    unsigned int k = g_cntbuf[p];

    float img0 = 0.0f, img1 = 0.0f, img2 = 0.0f;
    float dep = 0.0f;
    float Lsum = 0.0f;

    float c_end = (k > 0) ? g_S[s + k - 1] : 0.0f;
    for (unsigned int i = 0; i < k; i++) {
        float4 r = g_srec[s + i];
        float T = expf(c_end - g_S[s + i]);
        float contrib = r.y * T;
        unsigned int idx = __float_as_uint(r.z);
        img0 += contrib * feats[3 * idx + 0];
        img1 += contrib * feats[3 * idx + 1];
        img2 += contrib * feats[3 * idx + 2];
        dep  += contrib * r.x;
        Lsum += g_x[s + i];
    }

    out[0 * HW + p] = img0;
    out[1 * HW + p] = img1;
    out[2 * HW + p] = img2;
    out[3 * HW + p] = dep;
    out[4 * HW + p] = 1.0f - expf(Lsum);
}

// ---------------- launch ----------------
extern "C" void kernel_launch(void* const* d_in, const int* in_sizes, int n_in,
                              void* d_out, int out_size)
{
    const float* means = (const float*)d_in[0];
    const float* opac  = (const float*)d_in[1];
    const float* feats = (const float*)d_in[2];
    const float* pose  = (const float*)d_in[3];
    float* out = (float*)d_out;

    int n = in_sizes[0] / 3;

    void* cnt_addr = nullptr; cudaGetSymbolAddress(&cnt_addr, g_cntbuf);
    void* x_addr   = nullptr; cudaGetSymbolAddress(&x_addr, g_x);
    cudaMemsetAsync(cnt_addr, 0, (HW + 1) * sizeof(unsigned int), 0);
    cudaMemsetAsync(x_addr, 0, NPAD * sizeof(float), 0);

    int tpb = 256;
    project_count_kernel<<<(n + tpb - 1) / tpb, tpb>>>(means, opac, pose, n);
    scan_reduce_kernel<<<NSCAN_BLOCKS, SCAN_BLK>>>();
    scan_offsets_kernel<<<NSCAN_BLOCKS, SCAN_BLK>>>();
    place_kernel<<<NPAD / tpb, tpb>>>();
    sortemit_kernel<<<(HW + tpb - 1) / tpb, tpb>>>();
    scan_down_kernel<<<NCHUNK, 1024>>>();
    scan_mid_kernel<<<1, 256>>>();
    scan_up_kernel<<<NCHUNK, 1024>>>();
    render_kernel<<<(HW + tpb - 1) / tpb, tpb>>>(feats, out);
}

// round 5
// speedup vs baseline: 1.7227x; 1.7227x over previous
#include <cuda_runtime.h>
#include <cuda_bf16.h>
#include <math.h>

#define IMG_H 512
#define IMG_W 640
#define HW (IMG_H * IMG_W)            // 327680
#define FXc 500.0f
#define FYc 500.0f
#define CXc 320.0f
#define CYc 256.0f

#define SCAN_BLK 1024
#define NSCAN_BLOCKS (HW / SCAN_BLK)  // 320

#define NPAD 524288                   // 2^19 >= n_valid (~345k), power of two
#define NCHUNK 256                    // NPAD / 2048
#define KMAX 24                       // register-sort cap (Poisson lambda~1.05)

#define PRJ_TPB 256
#define PRJ_WARPS (PRJ_TPB / 32)

// ---------------- device scratch ----------------
__device__ unsigned int g_cntbuf[HW + 1];   // [HW] = nvalid append counter
__device__ unsigned int g_off[HW];
__device__ unsigned int g_woff[HW];
__device__ unsigned int g_bsum[NSCAN_BLOCKS];

__device__ float4 g_rec[NPAD];   // unordered: {pid_bits, z, w, idx_bits}
__device__ float4 g_srec[NPAD];  // binned+sorted: {z, w, idx_bits, unused}

__device__ float g_x[NPAD];      // lg = log1p(-w) at sorted positions (zero padded)
__device__ float g_S[NPAD];      // inclusive scan, assoc-scan rounding replicated
__device__ float g_L11[NCHUNK];
__device__ float g_S11[NCHUNK];

// ---------------- pass 1: project once, count + append compact records ----
// Projection arithmetic bit-identical to R1 (measured best):
// separate __fmul_rn/__fadd_rn, NO fma contraction.
// Append counter: ONE atomic per BLOCK (block-aggregated), not per warp.
__global__ void project_count_kernel(const float* __restrict__ means,
                                     const float* __restrict__ opac,
                                     const float* __restrict__ pose, int n)
{
    __shared__ unsigned int wcnt[PRJ_WARPS];
    __shared__ unsigned int woffs[PRJ_WARPS];
    __shared__ unsigned int sbase;

    int i = blockIdx.x * blockDim.x + threadIdx.x;
    int lane = threadIdx.x & 31;
    int warp = threadIdx.x >> 5;

    bool valid = false;
    float z = 0.0f, w = 0.0f;
    int pid = 0;
    if (i < n) {
        float m0 = means[3 * i + 0];
        float m1 = means[3 * i + 1];
        float m2 = means[3 * i + 2];
        // pose is identity: exact regardless of order
        float pc0 = m0 * pose[0] + m1 * pose[1] + m2 * pose[2]  + pose[3];
        float pc1 = m0 * pose[4] + m1 * pose[5] + m2 * pose[6]  + pose[7];
        z         = m0 * pose[8] + m1 * pose[9] + m2 * pose[10] + pose[11];
        // IEEE rn div/mul/add, NO fma (matches reference; R1-verified)
        float x = __fadd_rn(__fmul_rn(__fdiv_rn(pc0, z), FXc), CXc);
        float y = __fadd_rn(__fmul_rn(__fdiv_rn(pc1, z), FYc), CYc);
        valid = (x >= 0.0f) && (x < (float)IMG_W) &&
                (y >= 0.0f) && (y < (float)IMG_H) && (z > 0.0f);
        if (valid) {
            int xi = (int)floorf(x);
            int yi = (int)floorf(y);
            pid = yi * IMG_W + xi;
            w = opac[i];
        }
    }

    unsigned int mask = __ballot_sync(0xffffffffu, valid);
    if (lane == 0) wcnt[warp] = (unsigned int)__popc(mask);
    __syncthreads();
    if (threadIdx.x == 0) {
        unsigned int run = 0;
#pragma unroll
        for (int wi = 0; wi < PRJ_WARPS; wi++) {
            woffs[wi] = run;
            run += wcnt[wi];
        }
        sbase = (run > 0) ? atomicAdd(&g_cntbuf[HW], run) : 0u;
    }
    __syncthreads();

    if (valid) {
        unsigned int pos = sbase + woffs[warp] +
                           (unsigned int)__popc(mask & ((1u << lane) - 1u));
        atomicAdd(&g_cntbuf[pid], 1u);
        if (pos < NPAD)
            g_rec[pos] = make_float4(__int_as_float(pid), z, w,
                                     __int_as_float(i));
    }
}

// ---------------- offset scan: block sums ----------------
__global__ void scan_reduce_kernel()
{
    __shared__ unsigned int sh[SCAN_BLK];
    int t = threadIdx.x;
    sh[t] = g_cntbuf[blockIdx.x * SCAN_BLK + t];
    __syncthreads();
    for (int d = SCAN_BLK / 2; d > 0; d >>= 1) {
        if (t < d) sh[t] += sh[t + d];
        __syncthreads();
    }
    if (t == 0) g_bsum[blockIdx.x] = sh[0];
}

// ---------------- offset scan: full (redundant top scan per block) --------
__global__ void scan_offsets_kernel()
{
    __shared__ unsigned int sh[SCAN_BLK];
    __shared__ unsigned int tb[512];
    int t = threadIdx.x;
    int gi = blockIdx.x * SCAN_BLK + t;
    unsigned int v = g_cntbuf[gi];
    sh[t] = v;
    if (t < 512) tb[t] = (t < NSCAN_BLOCKS) ? g_bsum[t] : 0u;
    __syncthreads();
#pragma unroll
    for (int d = 1; d < SCAN_BLK; d <<= 1) {
        unsigned int add = (t >= d) ? sh[t - d] : 0u;
        unsigned int addt = (t < 512 && t >= d) ? tb[t - d] : 0u;
        __syncthreads();
        sh[t] += add;
        if (t < 512 && d < 512) tb[t] += addt;
        __syncthreads();
    }
    unsigned int bpref = (blockIdx.x > 0) ? tb[blockIdx.x - 1] : 0u;
    unsigned int o = sh[t] - v + bpref;
    g_off[gi] = o;
    g_woff[gi] = o;
}

// ---------------- pass 2: place records into bins ----------------
__global__ void place_kernel()
{
    unsigned int r = blockIdx.x * blockDim.x + threadIdx.x;
    if (r >= g_cntbuf[HW] || r >= NPAD) return;
    float4 rec = g_rec[r];
    int pid = __float_as_int(rec.x);
    unsigned int pos = atomicAdd(&g_woff[pid], 1u);
    if (pos < NPAD)
        g_srec[pos] = make_float4(rec.y, rec.z, rec.w, 0.0f);
}

// ---------------- per-pixel sort (z desc, idx asc) + emit lg --------------
__device__ __forceinline__ bool rec_before(const float4& a, const float4& b)
{
    if (a.x != b.x) return a.x > b.x;                   // z desc
    return __float_as_uint(a.z) < __float_as_uint(b.z); // idx asc (stable tie)
}

__global__ void sortemit_kernel()
{
    int p = blockIdx.x * blockDim.x + threadIdx.x;
    if (p >= HW) return;
    unsigned int s = g_off[p];
    unsigned int k = g_cntbuf[p];
    if (k == 0) return;
    if (k <= KMAX) {
        float4 a[KMAX];
        for (unsigned int i = 0; i < k; i++) a[i] = g_srec[s + i];
        for (unsigned int i = 1; i < k; i++) {
            float4 key = a[i];
            int j = (int)i - 1;
            while (j >= 0 && rec_before(key, a[j])) { a[j + 1] = a[j]; j--; }
            a[j + 1] = key;
        }
        for (unsigned int i = 0; i < k; i++) {
            g_srec[s + i] = a[i];
            g_x[s + i] = log1pf(-a[i].y);
        }
    } else {
        for (unsigned int i = 0; i < k; i++) {
            unsigned int best = i;
            float4 bv = g_srec[s + i];
            for (unsigned int j = i + 1; j < k; j++) {
                float4 cv = g_srec[s + j];
                if (rec_before(cv, bv)) { best = j; bv = cv; }
            }
            if (best != i) {
                float4 tmp = g_srec[s + i];
                g_srec[s + i] = bv;
                g_srec[s + best] = tmp;
            }
            g_x[s + i] = log1pf(-bv.y);
        }
    }
}

// ---------------- scan A: per-chunk pairwise tree sum (levels 1..11) ------
__global__ void scan_down_kernel()
{
    __shared__ float sh[2048];
    int t = threadIdx.x;               // 1024
    int base = blockIdx.x * 2048;
    sh[t] = g_x[base + t];
    sh[t + 1024] = g_x[base + t + 1024];
    __syncthreads();
    for (int size = 1024; size >= 1; size >>= 1) {
        float v = 0.0f;
        if (t < size) v = sh[2 * t] + sh[2 * t + 1];
        __syncthreads();
        if (t < size) sh[t] = v;
        __syncthreads();
    }
    if (t == 0) g_L11[blockIdx.x] = sh[0];
}

// ---------------- scan B: levels 12..19 + S11 (single block) --------------
__global__ void scan_mid_kernel()
{
    __shared__ float Lv[511];
    __shared__ float Sv[511];
    int t = threadIdx.x;               // 256
    Lv[t] = g_L11[t];
    __syncthreads();
    int off = 0, size = 256;
    for (int d = 0; d < 8; d++) {
        int noff = off + size, nsz = size >> 1;
        if (t < nsz) Lv[noff + t] = Lv[off + 2 * t] + Lv[off + 2 * t + 1];
        __syncthreads();
        off = noff; size = nsz;
    }
    if (t == 0) Sv[510] = Lv[510];
    __syncthreads();
    for (int d = 0; d < 8; d++) {
        int sz = 2 << d;
        off -= sz;
        int poff = off + sz;
        if (t < sz) {
            float v;
            if (t == 0)      v = Lv[off];
            else if (t & 1)  v = Sv[poff + ((t - 1) >> 1)];
            else             v = Sv[poff + (t >> 1) - 1] + Lv[off + t];
            Sv[off + t] = v;
        }
        __syncthreads();
    }
    g_S11[t] = Sv[t];
}

// ---------------- scan C: up-sweep, writes S (level 0) --------------------
__global__ void scan_up_kernel()
{
    __shared__ float Lb[4094];
    __shared__ float Sa[2048];
    __shared__ float Sb[1024];
    int t = threadIdx.x;               // 1024
    int b = blockIdx.x;
    int base = b * 2048;
    Lb[t] = g_x[base + t];
    Lb[t + 1024] = g_x[base + t + 1024];
    __syncthreads();
    int off = 0, size = 2048;
    for (int d = 1; d <= 10; d++) {
        int noff = off + size, nsz = size >> 1;
        for (int j = t; j < nsz; j += 1024)
            Lb[noff + j] = Lb[off + 2 * j] + Lb[off + 2 * j + 1];
        __syncthreads();
        off = noff; size = nsz;
    }
    float bound = (b > 0) ? g_S11[b - 1] : 0.0f;
    if (t == 0) {
        Sa[0] = (b == 0) ? Lb[off] : bound + Lb[off];
        Sa[1] = g_S11[b];
    }
    __syncthreads();
    for (int d = 9; d >= 0; d--) {
        int sz = 2048 >> d;
        off -= sz;
        float* Sprev = (d & 1) ? Sa : Sb;
        float* Scur  = (d & 1) ? Sb : Sa;
        for (int j = t; j < sz; j += 1024) {
            float v;
            if (j == 0)      v = (b == 0) ? Lb[off] : bound + Lb[off];
            else if (j & 1)  v = Sprev[(j - 1) >> 1];
            else             v = Sprev[(j >> 1) - 1] + Lb[off + j];
            Scur[j] = v;
        }
        __syncthreads();
    }
    g_S[base + t] = Sa[t];
    g_S[base + t + 1024] = Sa[t + 1024];
}

// ---------------- render ----------------
__global__ void render_kernel(const float* __restrict__ feats,
                              float* __restrict__ out)
{
    int p = blockIdx.x * blockDim.x + threadIdx.x;
    if (p >= HW) return;
    unsigned int s = g_off[p];
    unsigned int k = g_cntbuf[p];

    float img0 = 0.0f, img1 = 0.0f, img2 = 0.0f;
    float dep = 0.0f;
    float Lsum = 0.0f;

    float c_end = (k > 0) ? g_S[s + k - 1] : 0.0f;
    for (unsigned int i = 0; i < k; i++) {
        float4 r = g_srec[s + i];
        float T = expf(c_end - g_S[s + i]);
        float contrib = r.y * T;
        unsigned int idx = __float_as_uint(r.z);
        img0 += contrib * feats[3 * idx + 0];
        img1 += contrib * feats[3 * idx + 1];
        img2 += contrib * feats[3 * idx + 2];
        dep  += contrib * r.x;
        Lsum += g_x[s + i];
    }

    out[0 * HW + p] = img0;
    out[1 * HW + p] = img1;
    out[2 * HW + p] = img2;
    out[3 * HW + p] = dep;
    out[4 * HW + p] = 1.0f - expf(Lsum);
}

// ---------------- launch ----------------
extern "C" void kernel_launch(void* const* d_in, const int* in_sizes, int n_in,
                              void* d_out, int out_size)
{
    const float* means = (const float*)d_in[0];
    const float* opac  = (const float*)d_in[1];
    const float* feats = (const float*)d_in[2];
    const float* pose  = (const float*)d_in[3];
    float* out = (float*)d_out;

    int n = in_sizes[0] / 3;

    void* cnt_addr = nullptr; cudaGetSymbolAddress(&cnt_addr, g_cntbuf);
    void* x_addr   = nullptr; cudaGetSymbolAddress(&x_addr, g_x);
    cudaMemsetAsync(cnt_addr, 0, (HW + 1) * sizeof(unsigned int), 0);
    cudaMemsetAsync(x_addr, 0, NPAD * sizeof(float), 0);

    project_count_kernel<<<(n + PRJ_TPB - 1) / PRJ_TPB, PRJ_TPB>>>(means, opac, pose, n);
    scan_reduce_kernel<<<NSCAN_BLOCKS, SCAN_BLK>>>();
    scan_offsets_kernel<<<NSCAN_BLOCKS, SCAN_BLK>>>();
    place_kernel<<<NPAD / 256, 256>>>();
    sortemit_kernel<<<(HW + 255) / 256, 256>>>();
    scan_down_kernel<<<NCHUNK, 1024>>>();
    scan_mid_kernel<<<1, 256>>>();
    scan_up_kernel<<<NCHUNK, 1024>>>();
    render_kernel<<<(HW + 255) / 256, 256>>>(feats, out);
}